// round 17
// baseline (speedup 1.0000x reference)
#include <cuda_runtime.h>
#include <cuda_bf16.h>
#include <cooperative_groups.h>

namespace cgr = cooperative_groups;

// Fixed problem shapes
#define B_  4
#define T_  16
#define O_  32
#define H_  181
#define W_  360
#define BT_ (B_ * T_)          // 64 images
#define HW_ (H_ * W_)          // 65160 px

#define GAUSS_C (-0.5f / (2.5f * 2.5f + 1e-8f))
#define EPS_    1e-8f

// Windowed tables: 48 slots, valid at slots [8..40] (33 grid indices),
// slot s <-> grid index start + s - 8. Out-of-window slots hold 0, so a
// single unsigned clamp min((unsigned)x, 47) yields 0 for any out-of-window
// offset (negative wraps huge -> 47; >47 -> 47; slot 47 == 0).
#define WSLOT 48

#define NTHREADS 384           // 12 warps
#define CLUSTER  4             // 4 CTAs per image -> 2 CTAs per SM
#define NWARPS   (NTHREADS / 32)

// Image tiling: 12 row bands of 16 x 12 col strips of 32 = 144 warp-patches.
// CTA rank owns row bands [rank*3, rank*3+3). Warp w: band rank*3 + (w>>2),
// col strips {w&3, (w&3)+4, (w&3)+8}. 12 warps x 3 patches = 36 per CTA.

__global__ __launch_bounds__(NTHREADS, 2) __cluster_dims__(CLUSTER, 1, 1)
void traj_fused_kernel(const float* __restrict__ traj,
                       const float* __restrict__ lat,
                       const float* __restrict__ lon,
                       float* __restrict__ out)
{
    // 16B alignment REQUIRED: phase 1 stores float4 into slatw/slonw.
    __shared__ __align__(16) float slatw[O_ * WSLOT];   // 6 KB
    __shared__ __align__(16) float slonw[O_ * WSLOT];   // 6 KB
    __shared__ __align__(16) float sgrid[H_ + W_ + 3];  // lat[0..180], lon at H_
    __shared__ __align__(16) float straj[O_ * 2];
    __shared__ int   slats[O_];
    __shared__ int   slons[O_];
    __shared__ float sred[NWARPS];
    __shared__ float smax_all[CLUSTER];

    cgr::cluster_group cluster = cgr::this_cluster();
    const unsigned rank = cluster.block_rank();       // 0..3
    const int img = blockIdx.x >> 2;
    const int tid = threadIdx.x;

    // ---- Phase 0: overlapped staging (single LDG round) ----
    if (tid < O_ * 2) straj[tid] = traj[img * O_ * 2 + tid];
    for (int i = tid; i < H_ + W_; i += NTHREADS)
        sgrid[i] = (i < H_) ? lat[i] : lon[i - H_];
    __syncthreads();

    // ---- Phase 1: tables. Thread t: point t/12, slots (t%12)*8 .. +7.
    // 8 consecutive slots never straddle the 48-slot lat/lon boundary.
    {
        const int pl = tid / 12;
        const int s0 = (tid % 12) * 8;
        const bool is_lat = (s0 < WSLOT);
        const float coord = straj[pl * 2 + (is_lat ? 0 : 1)];
        const int start = is_lat
            ? (int)floorf(coord + 90.0f) - 16
            : (int)floorf((coord + 180.0f) * (359.0f / 360.0f)) - 16;
        const int t0   = is_lat ? s0 : s0 - WSLOT;
        const int gmax = is_lat ? H_ : W_;
        const int goff = is_lat ? 0 : H_;

        if (tid < O_) {
            slats[tid] = (int)floorf(straj[tid * 2 + 0] + 90.0f) - 16;
            slons[tid] = (int)floorf((straj[tid * 2 + 1] + 180.0f) * (359.0f / 360.0f)) - 16;
        }

        float vals[8];
        #pragma unroll
        for (int j = 0; j < 8; j++) {
            const int s  = t0 + j;
            const int gi = start + s - 8;
            const bool ok = (s >= 8) & (s <= 40) & (gi >= 0) & (gi < gmax);
            const float gc = sgrid[goff + min(max(gi, 0), gmax - 1)];
            const float d  = gc - coord;
            vals[j] = ok ? __expf(GAUSS_C * d * d) : 0.0f;
        }
        float* dst = is_lat ? &slatw[pl * WSLOT + t0] : &slonw[pl * WSLOT + t0];
        *reinterpret_cast<float4*>(dst)     = make_float4(vals[0], vals[1], vals[2], vals[3]);
        *reinterpret_cast<float4*>(dst + 4) = make_float4(vals[4], vals[5], vals[6], vals[7]);
    }
    __syncthreads();

    // ---- Geometry ----
    const int w  = tid >> 5, l = tid & 31;
    const int rg = l >> 2, cgi = l & 3;       // lane grid 8 x 4, tile 2 x 8
    const int band = (int)rank * 3 + (w >> 2);
    const int ws   = w & 3;                   // col strip base
    const int WR0  = band * 16;
    const int R0   = WR0 + rg * 2;
    const int tls = slats[l], tcs = slons[l]; // this lane's test point

    // Row half of the warp-footprint test is patch-invariant.
    const bool rowok = !(WR0 + 15 < tls || WR0 > tls + 32);

    // ---- Phase 2: gather into registers + local max ----
    float acc[3][2][8];
    #pragma unroll
    for (int pc = 0; pc < 3; pc++)
        #pragma unroll
        for (int j = 0; j < 2; j++)
            #pragma unroll
            for (int k = 0; k < 8; k++) acc[pc][j][k] = 0.0f;

    float lmax = 0.0f;
    #pragma unroll
    for (int pc = 0; pc < 3; pc++) {
        const int WC0 = (ws + pc * 4) * 32;   // warp footprint origin (cols)
        const int C0  = WC0 + cgi * 8;

        const bool act = rowok && !(WC0 + 31 < tcs || WC0 > tcs + 32);
        unsigned mask = __ballot_sync(0xFFFFFFFFu, act);

        for (; mask; mask &= (mask - 1)) {
            const int o = __ffs(mask) - 1;
            const int ls = slats[o], cs = slons[o];
            if (R0 + 1 < ls || R0 > ls + 32 || C0 + 7 < cs || C0 > cs + 32)
                continue;
            const int lbase = R0 + 8 - ls;
            const int cbase = C0 + 8 - cs;
            const float* lrow = &slatw[o * WSLOT];
            const float* crow = &slonw[o * WSLOT];
            float a[2], v[8];
            #pragma unroll
            for (int j = 0; j < 2; j++)
                a[j] = lrow[min((unsigned)(lbase + j), 47u)];
            #pragma unroll
            for (int k = 0; k < 8; k++)
                v[k] = crow[min((unsigned)(cbase + k), 47u)];
            #pragma unroll
            for (int j = 0; j < 2; j++)
                #pragma unroll
                for (int k = 0; k < 8; k++)
                    acc[pc][j][k] = fmaf(a[j], v[k], acc[pc][j][k]);
        }

        const bool colok = (C0 < W_);     // tile 8-aligned; W_ % 8 == 0
        #pragma unroll
        for (int j = 0; j < 2; j++) {
            if (colok && (R0 + j) < H_) {
                #pragma unroll
                for (int k = 0; k < 8; k++)
                    lmax = fmaxf(lmax, acc[pc][j][k]);
            }
        }
    }

    // ---- Max: warp shfl -> warp0 shfl -> DSMEM broadcast to all ranks ----
    #pragma unroll
    for (int off = 16; off > 0; off >>= 1)
        lmax = fmaxf(lmax, __shfl_xor_sync(0xFFFFFFFFu, lmax, off));
    if (l == 0) sred[w] = lmax;
    __syncthreads();
    if (tid < 32) {
        float v = (tid < NWARPS) ? sred[tid] : 0.0f;
        #pragma unroll
        for (int off = 16; off > 0; off >>= 1)
            v = fmaxf(v, __shfl_xor_sync(0xFFFFFFFFu, v, off));
        if (tid == 0) {
            #pragma unroll
            for (int r = 0; r < CLUSTER; r++) {
                float* dst = (float*)cluster.map_shared_rank(&smax_all[rank], r);
                *dst = v;
            }
        }
    }
    cluster.sync();
    const float mx = fmaxf(fmaxf(smax_all[0], smax_all[1]),
                           fmaxf(smax_all[2], smax_all[3]));
    const float inv = 1.0f / (mx + EPS_);

    // ---- Phase 3: scale registers and store ----
    float* oimg = out + img * HW_;
    #pragma unroll
    for (int pc = 0; pc < 3; pc++) {
        const int C0 = (ws + pc * 4) * 32 + cgi * 8;
        const bool colok = (C0 < W_);
        #pragma unroll
        for (int j = 0; j < 2; j++) {
            const int r = R0 + j;
            if (colok && r < H_) {
                float4 v0 = make_float4(acc[pc][j][0] * inv, acc[pc][j][1] * inv,
                                        acc[pc][j][2] * inv, acc[pc][j][3] * inv);
                float4 v1 = make_float4(acc[pc][j][4] * inv, acc[pc][j][5] * inv,
                                        acc[pc][j][6] * inv, acc[pc][j][7] * inv);
                *reinterpret_cast<float4*>(&oimg[r * W_ + C0])     = v0;
                *reinterpret_cast<float4*>(&oimg[r * W_ + C0 + 4]) = v1;
            }
        }
    }
}

// ---------------------------------------------------------------------------
extern "C" void kernel_launch(void* const* d_in, const int* in_sizes, int n_in,
                              void* d_out, int out_size)
{
    const float* traj = (const float*)d_in[0];  // (4,16,32,2)
    const float* lat  = (const float*)d_in[1];  // (181,)
    const float* lon  = (const float*)d_in[2];  // (360,)
    float* out = (float*)d_out;                 // (64,181,360) f32

    traj_fused_kernel<<<BT_ * CLUSTER, NTHREADS>>>(traj, lat, lon, out);
}